// round 3
// baseline (speedup 1.0000x reference)
#include <cuda_runtime.h>

#define CC 256           // feature dim (fixed for this problem)
#define MAXB 64          // safety headroom for num_batches

// Scratch: per-(batch, channel) partial sums. Device global (no allocs allowed).
__device__ float g_sums[MAXB * CC];

__global__ void zero_kernel(int n) {
    int i = blockIdx.x * blockDim.x + threadIdx.x;
    if (i < n) g_sums[i] = 0.0f;
}

// Accumulation: each block owns a contiguous row range [r0, r1).
// 256 threads: thread t handles channels [4*(t&63), +4) of rows r0 + (t>>6) + 4k.
// batch_idx is sorted, so per-thread the segment id changes rarely: keep a
// register accumulator and flush to global atomics (REDG) only on change/exit.
__global__ void __launch_bounds__(256) accum_kernel(
    const float* __restrict__ feat,
    const int*   __restrict__ bidx,
    const float* __restrict__ p_ptr,
    int n, int rows_per_block)
{
    const int c4    = (threadIdx.x & 63) * 4;
    const int rlane = threadIdx.x >> 6;          // 0..3 (warp-uniform)
    int r0 = blockIdx.x * rows_per_block;
    int r1 = r0 + rows_per_block;
    if (r1 > n) r1 = n;
    if (r0 >= n) return;

    const float p  = __ldg(p_ptr);
    const bool  p3 = (p == 3.0f);

    float a0 = 0.f, a1 = 0.f, a2 = 0.f, a3 = 0.f;
    int cur = -1;

    for (int r = r0 + rlane; r < r1; r += 4) {
        int b = __ldg(bidx + r);                 // warp-uniform -> broadcast
        if (b != cur) {
            if (cur >= 0) {
                float* s = g_sums + cur * CC + c4;
                atomicAdd(s + 0, a0); atomicAdd(s + 1, a1);
                atomicAdd(s + 2, a2); atomicAdd(s + 3, a3);
                a0 = a1 = a2 = a3 = 0.f;
            }
            cur = b;
        }
        float4 v = *reinterpret_cast<const float4*>(feat + (size_t)r * CC + c4);
        float x0 = fmaxf(v.x, 1e-6f);
        float x1 = fmaxf(v.y, 1e-6f);
        float x2 = fmaxf(v.z, 1e-6f);
        float x3 = fmaxf(v.w, 1e-6f);
        if (p3) {  // fast path: 2 FMUL/elem, fully hidden under HBM traffic
            a0 += x0 * x0 * x0;
            a1 += x1 * x1 * x1;
            a2 += x2 * x2 * x2;
            a3 += x3 * x3 * x3;
        } else {   // general path (correctness for arbitrary p)
            a0 += powf(x0, p);
            a1 += powf(x1, p);
            a2 += powf(x2, p);
            a3 += powf(x3, p);
        }
    }
    if (cur >= 0) {
        float* s = g_sums + cur * CC + c4;
        atomicAdd(s + 0, a0); atomicAdd(s + 1, a1);
        atomicAdd(s + 2, a2); atomicAdd(s + 3, a3);
    }
}

__device__ __forceinline__ int lower_bound_dev(const int* __restrict__ a, int n, int key) {
    int lo = 0, hi = n;
    while (lo < hi) {
        int mid = (lo + hi) >> 1;
        if (a[mid] < key) lo = mid + 1; else hi = mid;
    }
    return lo;
}

// Finalize: one block per batch row. Counts via binary search on sorted idx,
// mean^(1/p), then block L2 reduction and normalize.
__global__ void __launch_bounds__(CC) finalize_kernel(
    const int*   __restrict__ bidx,
    const float* __restrict__ p_ptr,
    int n, float* __restrict__ out)
{
    const int b = blockIdx.x;
    const int c = threadIdx.x;
    __shared__ float s_cnt;
    __shared__ float s_norm;
    __shared__ float red[CC / 32];

    if (c == 0) {
        int lo = lower_bound_dev(bidx, n, b);
        int hi = lower_bound_dev(bidx, n, b + 1);
        s_cnt = (float)(hi - lo);
    }
    __syncthreads();

    const float p    = __ldg(p_ptr);
    const float mean = g_sums[b * CC + c] / s_cnt;
    const float desc = powf(mean, 1.0f / p);

    float sq = desc * desc;
    #pragma unroll
    for (int o = 16; o; o >>= 1)
        sq += __shfl_xor_sync(0xffffffffu, sq, o);
    if ((c & 31) == 0) red[c >> 5] = sq;
    __syncthreads();
    if (c == 0) {
        float t = 0.f;
        #pragma unroll
        for (int i = 0; i < CC / 32; i++) t += red[i];
        s_norm = fmaxf(sqrtf(t), 1e-12f);
    }
    __syncthreads();

    out[b * CC + c] = desc / s_norm;
}

extern "C" void kernel_launch(void* const* d_in, const int* in_sizes, int n_in,
                              void* d_out, int out_size) {
    const float* feat  = (const float*)d_in[0];
    const float* p_ptr = (const float*)d_in[1];
    const int*   bidx  = (const int*)d_in[2];

    const int n = in_sizes[2];                 // N rows
    const int C = in_sizes[0] / n;             // feature dim (== 256 here)
    int B = out_size / C;                      // num batches
    if (B < 1) B = 1;
    if (B > MAXB) B = MAXB;

    float* out = (float*)d_out;

    // 1) zero scratch sums (must happen every replay)
    int zn = B * C;
    zero_kernel<<<(zn + 255) / 256, 256>>>(zn);

    // 2) accumulate x^p into per-(batch,channel) sums
    const int grid = 1184;                     // 148 SMs * 8 blocks
    const int rpb  = (n + grid - 1) / grid;
    accum_kernel<<<grid, 256>>>(feat, bidx, p_ptr, n, rpb);

    // 3) finalize: mean, pow(1/p), L2 normalize
    finalize_kernel<<<B, CC>>>(bidx, p_ptr, n, out);
}